// round 9
// baseline (speedup 1.0000x reference)
#include <cuda_runtime.h>
#include <cstdint>

// Householder reflection per row, B=8192, L=4096, fp32.
//   out[b,:] = z[b,:] - 2 * v[b,:] * (v.z)/(v.v)
//
// R7 base (61.9us, DRAM 83%): one CTA per row, TMA bulk loads into smem,
// per-thread __stcs stores. R8 showed concurrency > burst size.
// R9 change: shrink register footprint so 7 CTAs (not 5) fit per SM —
// only rv stays in registers; z is re-read from smem in the output pass
// (L1 pipe at 33% has headroom). More co-resident CTAs = more pending TMA
// streams = deeper DRAM queue.

constexpr int THREADS = 256;
constexpr int L       = 4096;
constexpr int L4      = L / 4;             // 1024 float4 per row
constexpr int PER     = L4 / THREADS;      // 4 float4 per thread per tensor
constexpr int ROW_BYTES   = L * 4;         // 16384
constexpr int STAGE_BYTES = 2 * ROW_BYTES; // 32768 (v + z)

__device__ __forceinline__ uint32_t smem_u32(const void* p) {
    return (uint32_t)__cvta_generic_to_shared(p);
}

__global__ __launch_bounds__(THREADS, 7)
void hh_tma_r9_kernel(const float4* __restrict__ v,
                      const float4* __restrict__ z,
                      float4* __restrict__ out)
{
    extern __shared__ float4 sm[];            // v: [0,1024), z: [1024,2048)
    __shared__ __align__(8) unsigned long long mbar;
    __shared__ float s_part[16];              // 8 warps x {vz, vv}
    __shared__ float s_scale;

    const int t    = threadIdx.x;
    const int lane = t & 31;
    const int wid  = t >> 5;
    const size_t base = (size_t)blockIdx.x * L4;

    const uint32_t mb = smem_u32(&mbar);

    if (t == 0) {
        asm volatile("mbarrier.init.shared::cta.b64 [%0], %1;"
                     :: "r"(mb), "r"(1));
        asm volatile("fence.proxy.async.shared::cta;" ::: "memory");
    }
    __syncthreads();

    if (t == 0) {
        asm volatile("mbarrier.arrive.expect_tx.shared::cta.b64 _, [%0], %1;"
                     :: "r"(mb), "r"(STAGE_BYTES) : "memory");
        asm volatile("cp.async.bulk.shared::cta.global.mbarrier::complete_tx::bytes"
                     " [%0], [%1], %2, [%3];"
                     :: "r"(smem_u32(sm)), "l"(v + base), "r"(ROW_BYTES), "r"(mb)
                     : "memory");
        asm volatile("cp.async.bulk.shared::cta.global.mbarrier::complete_tx::bytes"
                     " [%0], [%1], %2, [%3];"
                     :: "r"(smem_u32(sm + L4)), "l"(z + base), "r"(ROW_BYTES), "r"(mb)
                     : "memory");
    }

    // Wait (parity 0, single-shot), acquire for generic smem reads
    {
        uint32_t done;
        asm volatile(
            "{\n\t.reg .pred p;\n\t"
            "mbarrier.try_wait.parity.acquire.cta.shared::cta.b64 p, [%1], %2;\n\t"
            "selp.b32 %0, 1, 0, p;\n\t}"
            : "=r"(done) : "r"(mb), "r"(0) : "memory");
        while (!done) {
            asm volatile(
                "{\n\t.reg .pred p;\n\t"
                "mbarrier.try_wait.parity.acquire.cta.shared::cta.b64 p, [%1], %2, 0x989680;\n\t"
                "selp.b32 %0, 1, 0, p;\n\t}"
                : "=r"(done) : "r"(mb), "r"(0) : "memory");
        }
    }

    // Dot pass: keep only rv in registers; z read once here, re-read later
    float4 rv[PER];
    float dvz = 0.0f, dvv = 0.0f;
    #pragma unroll
    for (int i = 0; i < PER; i++) {
        rv[i] = sm[t + i * THREADS];
        const float4 b = sm[L4 + t + i * THREADS];
        dvz += rv[i].x * b.x + rv[i].y * b.y + rv[i].z * b.z + rv[i].w * b.w;
        dvv += rv[i].x * rv[i].x + rv[i].y * rv[i].y
             + rv[i].z * rv[i].z + rv[i].w * rv[i].w;
    }

    #pragma unroll
    for (int off = 16; off > 0; off >>= 1) {
        dvz += __shfl_xor_sync(0xFFFFFFFFu, dvz, off);
        dvv += __shfl_xor_sync(0xFFFFFFFFu, dvv, off);
    }
    if (lane == 0) { s_part[wid] = dvz; s_part[8 + wid] = dvv; }
    __syncthreads();

    if (wid == 0) {
        float a = (lane < 8) ? s_part[lane] : 0.0f;
        float c = (lane < 8) ? s_part[8 + lane] : 0.0f;
        #pragma unroll
        for (int off = 4; off > 0; off >>= 1) {
            a += __shfl_xor_sync(0xFFFFFFFFu, a, off);
            c += __shfl_xor_sync(0xFFFFFFFFu, c, off);
        }
        if (lane == 0) s_scale = 2.0f * a / c;
    }
    __syncthreads();

    const float nscale = -s_scale;
    float4* og = out + base;

    // Output pass: z re-read from smem, v from registers
    #pragma unroll
    for (int i = 0; i < PER; i++) {
        const float4 b = sm[L4 + t + i * THREADS];
        float4 o;
        o.x = fmaf(nscale, rv[i].x, b.x);
        o.y = fmaf(nscale, rv[i].y, b.y);
        o.z = fmaf(nscale, rv[i].z, b.z);
        o.w = fmaf(nscale, rv[i].w, b.w);
        __stcs(og + t + i * THREADS, o);
    }
}

extern "C" void kernel_launch(void* const* d_in, const int* in_sizes, int n_in,
                              void* d_out, int out_size)
{
    const float4* v = (const float4*)d_in[0];
    const float4* z = (const float4*)d_in[1];
    float4* out = (float4*)d_out;

    const int B = in_sizes[0] / L;    // 8192

    static bool attr_set = false;
    if (!attr_set) {
        cudaFuncSetAttribute(hh_tma_r9_kernel,
                             cudaFuncAttributeMaxDynamicSharedMemorySize,
                             STAGE_BYTES);
        attr_set = true;
    }

    hh_tma_r9_kernel<<<B, THREADS, STAGE_BYTES>>>(v, z, out);
}

// round 10
// speedup vs baseline: 1.0020x; 1.0020x over previous
#include <cuda_runtime.h>
#include <cstdint>

// Householder reflection per row, B=8192, L=4096, fp32.
//   out[b,:] = z[b,:] - 2 * v[b,:] * (v.z)/(v.v)
//
// R7 base (best wall 61.9us = 6.50 TB/s sustained): one CTA per row, TMA
// bulk loads into smem, register-resident payload, single smem pass.
// R10 change: L2 policy management for the mixed read/write stream —
//  * bulk loads carry an evict_first L2 policy (read lines have zero reuse;
//    stop them evicting pending-writeback output lines),
//  * stores use default evict_normal (NOT __stcs) so L2 buffers writes and
//    drains smoothly instead of being forced out early against the reads.

constexpr int THREADS = 256;
constexpr int L       = 4096;
constexpr int L4      = L / 4;             // 1024 float4 per row
constexpr int PER     = L4 / THREADS;      // 4 float4 per thread per tensor
constexpr int ROW_BYTES   = L * 4;         // 16384
constexpr int STAGE_BYTES = 2 * ROW_BYTES; // 32768 (v + z)

__device__ __forceinline__ uint32_t smem_u32(const void* p) {
    return (uint32_t)__cvta_generic_to_shared(p);
}

__global__ __launch_bounds__(THREADS)
void hh_tma_r10_kernel(const float4* __restrict__ v,
                       const float4* __restrict__ z,
                       float4* __restrict__ out)
{
    extern __shared__ float4 sm[];            // v: [0,1024), z: [1024,2048)
    __shared__ __align__(8) unsigned long long mbar;
    __shared__ float s_part[16];              // 8 warps x {vz, vv}
    __shared__ float s_scale;

    const int t    = threadIdx.x;
    const int lane = t & 31;
    const int wid  = t >> 5;
    const size_t base = (size_t)blockIdx.x * L4;

    const uint32_t mb = smem_u32(&mbar);

    if (t == 0) {
        asm volatile("mbarrier.init.shared::cta.b64 [%0], %1;"
                     :: "r"(mb), "r"(1));
        asm volatile("fence.proxy.async.shared::cta;" ::: "memory");
    }
    __syncthreads();

    if (t == 0) {
        // Read lines are single-use: evict_first so they don't push
        // pending-writeback output lines out of L2.
        uint64_t pol;
        asm volatile("createpolicy.fractional.L2::evict_first.b64 %0, 1.0;"
                     : "=l"(pol));
        asm volatile("mbarrier.arrive.expect_tx.shared::cta.b64 _, [%0], %1;"
                     :: "r"(mb), "r"(STAGE_BYTES) : "memory");
        asm volatile("cp.async.bulk.shared::cta.global.mbarrier::complete_tx::bytes"
                     ".L2::cache_hint [%0], [%1], %2, [%3], %4;"
                     :: "r"(smem_u32(sm)), "l"(v + base), "r"(ROW_BYTES),
                        "r"(mb), "l"(pol) : "memory");
        asm volatile("cp.async.bulk.shared::cta.global.mbarrier::complete_tx::bytes"
                     ".L2::cache_hint [%0], [%1], %2, [%3], %4;"
                     :: "r"(smem_u32(sm + L4)), "l"(z + base), "r"(ROW_BYTES),
                        "r"(mb), "l"(pol) : "memory");
    }

    // Wait (parity 0, single-shot), acquire for generic smem reads
    {
        uint32_t done;
        asm volatile(
            "{\n\t.reg .pred p;\n\t"
            "mbarrier.try_wait.parity.acquire.cta.shared::cta.b64 p, [%1], %2;\n\t"
            "selp.b32 %0, 1, 0, p;\n\t}"
            : "=r"(done) : "r"(mb), "r"(0) : "memory");
        while (!done) {
            asm volatile(
                "{\n\t.reg .pred p;\n\t"
                "mbarrier.try_wait.parity.acquire.cta.shared::cta.b64 p, [%1], %2, 0x989680;\n\t"
                "selp.b32 %0, 1, 0, p;\n\t}"
                : "=r"(done) : "r"(mb), "r"(0) : "memory");
        }
    }

    // Single smem pass: payload into registers, both dots accumulated
    float4 rv[PER], rz[PER];
    float dvz = 0.0f, dvv = 0.0f;
    #pragma unroll
    for (int i = 0; i < PER; i++) {
        rv[i] = sm[t + i * THREADS];
        rz[i] = sm[L4 + t + i * THREADS];
        dvz += rv[i].x * rz[i].x + rv[i].y * rz[i].y
             + rv[i].z * rz[i].z + rv[i].w * rz[i].w;
        dvv += rv[i].x * rv[i].x + rv[i].y * rv[i].y
             + rv[i].z * rv[i].z + rv[i].w * rv[i].w;
    }

    #pragma unroll
    for (int off = 16; off > 0; off >>= 1) {
        dvz += __shfl_xor_sync(0xFFFFFFFFu, dvz, off);
        dvv += __shfl_xor_sync(0xFFFFFFFFu, dvv, off);
    }
    if (lane == 0) { s_part[wid] = dvz; s_part[8 + wid] = dvv; }
    __syncthreads();

    if (wid == 0) {
        float a = (lane < 8) ? s_part[lane] : 0.0f;
        float c = (lane < 8) ? s_part[8 + lane] : 0.0f;
        #pragma unroll
        for (int off = 4; off > 0; off >>= 1) {
            a += __shfl_xor_sync(0xFFFFFFFFu, a, off);
            c += __shfl_xor_sync(0xFFFFFFFFu, c, off);
        }
        if (lane == 0) s_scale = 2.0f * a / c;
    }
    __syncthreads();

    const float nscale = -s_scale;
    float4* og = out + base;

    // Output from registers; default (evict_normal) stores — let L2 buffer
    #pragma unroll
    for (int i = 0; i < PER; i++) {
        float4 o;
        o.x = fmaf(nscale, rv[i].x, rz[i].x);
        o.y = fmaf(nscale, rv[i].y, rz[i].y);
        o.z = fmaf(nscale, rv[i].z, rz[i].z);
        o.w = fmaf(nscale, rv[i].w, rz[i].w);
        og[t + i * THREADS] = o;
    }
}

extern "C" void kernel_launch(void* const* d_in, const int* in_sizes, int n_in,
                              void* d_out, int out_size)
{
    const float4* v = (const float4*)d_in[0];
    const float4* z = (const float4*)d_in[1];
    float4* out = (float4*)d_out;

    const int B = in_sizes[0] / L;    // 8192

    static bool attr_set = false;
    if (!attr_set) {
        cudaFuncSetAttribute(hh_tma_r10_kernel,
                             cudaFuncAttributeMaxDynamicSharedMemorySize,
                             STAGE_BYTES);
        attr_set = true;
    }

    hh_tma_r10_kernel<<<B, THREADS, STAGE_BYTES>>>(v, z, out);
}

// round 11
// speedup vs baseline: 1.0284x; 1.0264x over previous
#include <cuda_runtime.h>
#include <cstdint>

// Householder reflection per row, B=8192, L=4096, fp32.
//   out[b,:] = z[b,:] - 2 * v[b,:] * (v.z)/(v.v)
//
// R7 base (best wall 61.9us, DRAM 83%, sustained 6.5 TB/s): one CTA per row,
// cp.async.bulk loads into smem, register-resident payload, __stcs stores.
// R11 change: two half-row mbarrier stages — dot accumulation starts on the
// first 8KB halves while the second halves are still streaming. Cuts per-CTA
// end-to-end latency ~40%, shrinking wave ramp/tail (the wall-vs-ncu gap).

constexpr int THREADS = 256;
constexpr int L       = 4096;
constexpr int L4      = L / 4;             // 1024 float4 per row
constexpr int PER     = L4 / THREADS;      // 4 float4 per thread per tensor
constexpr int HALF    = PER / 2;           // 2 per half
constexpr int H4      = L4 / 2;            // 512 float4 per half-row
constexpr int ROW_BYTES    = L * 4;        // 16384
constexpr int HALF_BYTES   = ROW_BYTES / 2;       // 8192
constexpr int STAGE_BYTES  = 2 * ROW_BYTES;       // 32768 (v + z)

__device__ __forceinline__ uint32_t smem_u32(const void* p) {
    return (uint32_t)__cvta_generic_to_shared(p);
}

__device__ __forceinline__ void mbar_wait0(uint32_t mb) {
    uint32_t done;
    asm volatile(
        "{\n\t.reg .pred p;\n\t"
        "mbarrier.try_wait.parity.acquire.cta.shared::cta.b64 p, [%1], %2;\n\t"
        "selp.b32 %0, 1, 0, p;\n\t}"
        : "=r"(done) : "r"(mb), "r"(0) : "memory");
    while (!done) {
        asm volatile(
            "{\n\t.reg .pred p;\n\t"
            "mbarrier.try_wait.parity.acquire.cta.shared::cta.b64 p, [%1], %2, 0x989680;\n\t"
            "selp.b32 %0, 1, 0, p;\n\t}"
            : "=r"(done) : "r"(mb), "r"(0) : "memory");
    }
}

__global__ __launch_bounds__(THREADS)
void hh_tma_r11_kernel(const float4* __restrict__ v,
                       const float4* __restrict__ z,
                       float4* __restrict__ out)
{
    extern __shared__ float4 sm[];            // v: [0,1024), z: [1024,2048)
    __shared__ __align__(8) unsigned long long mbar0;
    __shared__ __align__(8) unsigned long long mbar1;
    __shared__ float s_part[16];              // 8 warps x {vz, vv}
    __shared__ float s_scale;

    const int t    = threadIdx.x;
    const int lane = t & 31;
    const int wid  = t >> 5;
    const size_t base = (size_t)blockIdx.x * L4;

    const uint32_t mb0 = smem_u32(&mbar0);
    const uint32_t mb1 = smem_u32(&mbar1);

    if (t == 0) {
        asm volatile("mbarrier.init.shared::cta.b64 [%0], %1;" :: "r"(mb0), "r"(1));
        asm volatile("mbarrier.init.shared::cta.b64 [%0], %1;" :: "r"(mb1), "r"(1));
        asm volatile("fence.proxy.async.shared::cta;" ::: "memory");
    }
    __syncthreads();

    if (t == 0) {
        // Stage 0: first halves of v and z
        asm volatile("mbarrier.arrive.expect_tx.shared::cta.b64 _, [%0], %1;"
                     :: "r"(mb0), "r"(2 * HALF_BYTES) : "memory");
        asm volatile("cp.async.bulk.shared::cta.global.mbarrier::complete_tx::bytes"
                     " [%0], [%1], %2, [%3];"
                     :: "r"(smem_u32(sm)), "l"(v + base),
                        "r"(HALF_BYTES), "r"(mb0) : "memory");
        asm volatile("cp.async.bulk.shared::cta.global.mbarrier::complete_tx::bytes"
                     " [%0], [%1], %2, [%3];"
                     :: "r"(smem_u32(sm + L4)), "l"(z + base),
                        "r"(HALF_BYTES), "r"(mb0) : "memory");
        // Stage 1: second halves
        asm volatile("mbarrier.arrive.expect_tx.shared::cta.b64 _, [%0], %1;"
                     :: "r"(mb1), "r"(2 * HALF_BYTES) : "memory");
        asm volatile("cp.async.bulk.shared::cta.global.mbarrier::complete_tx::bytes"
                     " [%0], [%1], %2, [%3];"
                     :: "r"(smem_u32(sm + H4)), "l"(v + base + H4),
                        "r"(HALF_BYTES), "r"(mb1) : "memory");
        asm volatile("cp.async.bulk.shared::cta.global.mbarrier::complete_tx::bytes"
                     " [%0], [%1], %2, [%3];"
                     :: "r"(smem_u32(sm + L4 + H4)), "l"(z + base + H4),
                        "r"(HALF_BYTES), "r"(mb1) : "memory");
    }

    float4 rv[PER], rz[PER];
    float dvz = 0.0f, dvv = 0.0f;

    // ---- Half 0: compute while half 1 still streams ----
    mbar_wait0(mb0);
    #pragma unroll
    for (int i = 0; i < HALF; i++) {
        rv[i] = sm[t + i * THREADS];
        rz[i] = sm[L4 + t + i * THREADS];
        dvz += rv[i].x * rz[i].x + rv[i].y * rz[i].y
             + rv[i].z * rz[i].z + rv[i].w * rz[i].w;
        dvv += rv[i].x * rv[i].x + rv[i].y * rv[i].y
             + rv[i].z * rv[i].z + rv[i].w * rv[i].w;
    }

    // ---- Half 1 ----
    mbar_wait0(mb1);
    #pragma unroll
    for (int i = HALF; i < PER; i++) {
        rv[i] = sm[H4 + t + (i - HALF) * THREADS];
        rz[i] = sm[L4 + H4 + t + (i - HALF) * THREADS];
        dvz += rv[i].x * rz[i].x + rv[i].y * rz[i].y
             + rv[i].z * rz[i].z + rv[i].w * rz[i].w;
        dvv += rv[i].x * rv[i].x + rv[i].y * rv[i].y
             + rv[i].z * rv[i].z + rv[i].w * rv[i].w;
    }

    #pragma unroll
    for (int off = 16; off > 0; off >>= 1) {
        dvz += __shfl_xor_sync(0xFFFFFFFFu, dvz, off);
        dvv += __shfl_xor_sync(0xFFFFFFFFu, dvv, off);
    }
    if (lane == 0) { s_part[wid] = dvz; s_part[8 + wid] = dvv; }
    __syncthreads();

    if (wid == 0) {
        float a = (lane < 8) ? s_part[lane] : 0.0f;
        float c = (lane < 8) ? s_part[8 + lane] : 0.0f;
        #pragma unroll
        for (int off = 4; off > 0; off >>= 1) {
            a += __shfl_xor_sync(0xFFFFFFFFu, a, off);
            c += __shfl_xor_sync(0xFFFFFFFFu, c, off);
        }
        if (lane == 0) s_scale = 2.0f * a / c;
    }
    __syncthreads();

    const float nscale = -s_scale;
    float4* og = out + base;

    #pragma unroll
    for (int i = 0; i < HALF; i++) {
        float4 o;
        o.x = fmaf(nscale, rv[i].x, rz[i].x);
        o.y = fmaf(nscale, rv[i].y, rz[i].y);
        o.z = fmaf(nscale, rv[i].z, rz[i].z);
        o.w = fmaf(nscale, rv[i].w, rz[i].w);
        __stcs(og + t + i * THREADS, o);
    }
    #pragma unroll
    for (int i = HALF; i < PER; i++) {
        float4 o;
        o.x = fmaf(nscale, rv[i].x, rz[i].x);
        o.y = fmaf(nscale, rv[i].y, rz[i].y);
        o.z = fmaf(nscale, rv[i].z, rz[i].z);
        o.w = fmaf(nscale, rv[i].w, rz[i].w);
        __stcs(og + H4 + t + (i - HALF) * THREADS, o);
    }
}

extern "C" void kernel_launch(void* const* d_in, const int* in_sizes, int n_in,
                              void* d_out, int out_size)
{
    const float4* v = (const float4*)d_in[0];
    const float4* z = (const float4*)d_in[1];
    float4* out = (float4*)d_out;

    const int B = in_sizes[0] / L;    // 8192

    static bool attr_set = false;
    if (!attr_set) {
        cudaFuncSetAttribute(hh_tma_r11_kernel,
                             cudaFuncAttributeMaxDynamicSharedMemorySize,
                             STAGE_BYTES);
        attr_set = true;
    }

    hh_tma_r11_kernel<<<B, THREADS, STAGE_BYTES>>>(v, z, out);
}